// round 14
// baseline (speedup 1.0000x reference)
#include <cuda_runtime.h>
#include <cstdint>

#define NB 16      // batch
#define NS 512     // seq
#define NH 384     // hidden
#define NL 2000    // max_mel_len
#define NBINS 256
#define H4 (NH/4)  // 96 float4 per row

#define TR 16                       // tile rows per CTA (125 tiles per batch row)
#define NT 384                      // threads per CTA

// Fused single kernel. grid (125, 16), block (96, 4).
// Lightweight per-CTA prologue: smem durations -> single-warp scan ->
// binary-search seg -> gather + direct STG. Two block barriers total.
__global__ void __launch_bounds__(NT) fused_kernel(
    const float4* __restrict__ enc,
    const float*  __restrict__ ldur,
    const float*  __restrict__ pitch,
    const float*  __restrict__ energy,
    const float4* __restrict__ pemb,
    const float4* __restrict__ eemb,
    float4* __restrict__ out,
    float* __restrict__ out_tail, int write_tail)
{
    __shared__ int   sc[NS];         // durations, then inclusive cumsum (2 KB)
    __shared__ float wred[2][12];    // per-warp partial sums (pitch, energy)
    __shared__ int   s_pe[2];        // pitch idx, energy idx

    const int q   = threadIdx.x;                // 0..95
    const int yy  = threadIdx.y;                // 0..3
    const int tid = yy * 96 + q;                // 0..383
    const int b   = blockIdx.y;                 // 0..15
    const int l0  = blockIdx.x * TR;            // tile base row
    const int r0  = yy * 4;                     // my 4 consecutive rows
    const int lane = tid & 31;
    const int warp = tid >> 5;                  // 0..11

    // ---- phase 1: durations -> smem, pitch/energy partial sums ----
    float ps = 0.f, es = 0.f;
    #pragma unroll
    for (int i = tid; i < NS; i += NT) {
        const float ld = ldur[b * NS + i];
        sc[i] = (int)fmaxf(rintf(expf(ld) - 1.0f), 0.0f);
        ps += pitch[b * NS + i];
        es += energy[b * NS + i];
    }
    #pragma unroll
    for (int off = 16; off > 0; off >>= 1) {
        ps += __shfl_xor_sync(0xffffffffu, ps, off);
        es += __shfl_xor_sync(0xffffffffu, es, off);
    }
    if (lane == 0) { wred[0][warp] = ps; wred[1][warp] = es; }
    __syncthreads();

    // ---- phase 2: warp 0 scans 512 elems; warp 1 finalizes means ----
    if (warp == 0) {
        // 16 contiguous elems per lane via 4x int4 LDS
        int4 a0 = ((const int4*)sc)[lane * 4 + 0];
        int4 a1 = ((const int4*)sc)[lane * 4 + 1];
        int4 a2 = ((const int4*)sc)[lane * 4 + 2];
        int4 a3 = ((const int4*)sc)[lane * 4 + 3];
        // serial local inclusive prefix over the 16
        a0.y += a0.x; a0.z += a0.y; a0.w += a0.z;
        a1.x += a0.w; a1.y += a1.x; a1.z += a1.y; a1.w += a1.z;
        a2.x += a1.w; a2.y += a2.x; a2.z += a2.y; a2.w += a2.z;
        a3.x += a2.w; a3.y += a3.x; a3.z += a3.y; a3.w += a3.z;
        // cross-lane exclusive offset from inclusive shfl scan of totals
        const int tot = a3.w;
        int inc = tot;
        #pragma unroll
        for (int off = 1; off < 32; off <<= 1) {
            int y = __shfl_up_sync(0xffffffffu, inc, off);
            if (lane >= off) inc += y;
        }
        const int excl = inc - tot;
        a0.x += excl; a0.y += excl; a0.z += excl; a0.w += excl;
        a1.x += excl; a1.y += excl; a1.z += excl; a1.w += excl;
        a2.x += excl; a2.y += excl; a2.z += excl; a2.w += excl;
        a3.x += excl; a3.y += excl; a3.z += excl; a3.w += excl;
        ((int4*)sc)[lane * 4 + 0] = a0;
        ((int4*)sc)[lane * 4 + 1] = a1;
        ((int4*)sc)[lane * 4 + 2] = a2;
        ((int4*)sc)[lane * 4 + 3] = a3;
    } else if (warp == 1 && lane < 2) {
        float s = 0.f;
        #pragma unroll
        for (int i = 0; i < 12; i++) s += wred[lane][i];
        s_pe[lane] = min(max((int)(s * (1.0f / NS)), 0), NBINS - 1);
    }
    __syncthreads();

    // ---- phase 3: derive parameters ----
    const int ml = min(sc[NS - 1], NL);
    if (write_tail && blockIdx.x == 0 && tid == 0)
        out_tail[b] = (float)ml;

    // seg for my 4 rows: binary lower-bound (first s with cum[s] > l).
    // 4 independent searches interleave (MLP 4). Group-uniform -> LDS bcast.
    int sv[4];
    #pragma unroll
    for (int i = 0; i < 4; i++) sv[i] = 0;
    #pragma unroll
    for (int step = 256; step > 0; step >>= 1) {
        #pragma unroll
        for (int i = 0; i < 4; i++) {
            const int l = l0 + r0 + i;
            if (sc[sv[i] + step - 1] <= l) sv[i] += step;
        }
    }

    // ---- phase 4: comb + gather + masked add + direct stores ----
    const int pidx = s_pe[0];
    const int eidx = s_pe[1];
    const float4 pv = __ldg(&pemb[pidx * H4 + q]);
    const float4 ew = __ldg(&eemb[eidx * H4 + q]);
    float4 c;
    c.x = pv.x + ew.x; c.y = pv.y + ew.y;
    c.z = pv.z + ew.z; c.w = pv.w + ew.w;

    const float4* __restrict__ encb = enc + b * (NS * H4);
    float4 ev[4];
    #pragma unroll
    for (int i = 0; i < 4; i++) {
        const int s = min(sv[i], NS - 1);
        ev[i] = __ldg(&encb[s * H4 + q]);
    }

    float4* const outp = out + (size_t)(b * NL + l0 + r0) * H4 + q;
    #pragma unroll
    for (int i = 0; i < 4; i++) {
        const float m = (l0 + r0 + i < ml) ? 1.0f : 0.0f;
        float4 v;
        v.x = fmaf(m, ev[i].x, c.x);
        v.y = fmaf(m, ev[i].y, c.y);
        v.z = fmaf(m, ev[i].z, c.z);
        v.w = fmaf(m, ev[i].w, c.w);
        outp[i * H4] = v;
    }
}

extern "C" void kernel_launch(void* const* d_in, const int* in_sizes, int n_in,
                              void* d_out, int out_size)
{
    const float* enc   = (const float*)d_in[0];  // (B,S,H)
    const float* ldur  = (const float*)d_in[1];  // (B,S)
    const float* pitch = (const float*)d_in[2];  // (B,S)
    const float* energ = (const float*)d_in[3];  // (B,S)
    const float* pemb  = (const float*)d_in[4];  // (256,H)
    const float* eemb  = (const float*)d_in[5];  // (256,H)

    float* out = (float*)d_out;
    const int main_elems = NB * NL * NH;
    const int write_tail = (out_size >= main_elems + NB) ? 1 : 0;

    dim3 grid(NL / TR, NB);      // 125 x 16 = 2000 CTAs
    dim3 block(96, 4);
    fused_kernel<<<grid, block>>>(
        (const float4*)enc, ldur, pitch, energ,
        (const float4*)pemb, (const float4*)eemb,
        (float4*)out, out + main_elems, write_tail);
}

// round 15
// speedup vs baseline: 1.1532x; 1.1532x over previous
#include <cuda_runtime.h>
#include <cstdint>

#define NB 16      // batch
#define NS 512     // seq
#define NH 384     // hidden
#define NL 2000    // max_mel_len
#define NBINS 256
#define H4 (NH/4)  // 96 float4 per row

#define TR 16                       // tile rows per CTA (125 tiles per batch row)

// scratch (no allocation allowed in kernel_launch)
__device__ int    g_seg[NB * NL];
__device__ int    g_mellen[NB];
__device__ float4 g_comb[NB * H4];   // pemb[pi_b] + eemb[ei_b]

// One block per batch row, 512 threads (one per source token).
__global__ void __launch_bounds__(NS) prep_kernel(
    const float* __restrict__ log_duration,
    const float* __restrict__ pitch,
    const float* __restrict__ energy,
    const float4* __restrict__ pemb,
    const float4* __restrict__ eemb,
    float* __restrict__ out_tail, int write_tail)
{
    const int b    = blockIdx.x;
    const int tid  = threadIdx.x;
    const int warp = tid >> 5;
    const int lane = tid & 31;

    __shared__ int   wsum[16];
    __shared__ float wred[16];
    __shared__ int   s_pidx, s_eidx;

    // duration = max(round(exp(ld) - 1), 0)
    const float ld = log_duration[b * NS + tid];
    const int d = (int)fmaxf(rintf(expf(ld) - 1.0f), 0.0f);

    // ---- inclusive scan over S=512: warp shfl scan + cross-warp ----
    int x = d;
    #pragma unroll
    for (int off = 1; off < 32; off <<= 1) {
        int y = __shfl_up_sync(0xffffffffu, x, off);
        if (lane >= off) x += y;
    }
    if (lane == 31) wsum[warp] = x;
    __syncthreads();
    if (warp == 0 && lane < 16) {
        int v = wsum[lane];
        #pragma unroll
        for (int off = 1; off < 16; off <<= 1) {
            int y = __shfl_up_sync(0x0000ffffu, v, off);
            if (lane >= off) v += y;
        }
        wsum[lane] = v;
    }
    __syncthreads();
    const int cum   = x + (warp ? wsum[warp - 1] : 0);
    const int start = cum - d;
    const int total = wsum[15];

    // ---- pitch / energy means via shfl reductions ----
    float p = pitch[b * NS + tid];
    float e = energy[b * NS + tid];
    #pragma unroll
    for (int off = 16; off > 0; off >>= 1) {
        p += __shfl_xor_sync(0xffffffffu, p, off);
        e += __shfl_xor_sync(0xffffffffu, e, off);
    }
    if (lane == 0) wred[warp] = p;
    __syncthreads();
    if (tid == 0) {
        float s = 0.f;
        #pragma unroll
        for (int i = 0; i < 16; i++) s += wred[i];
        s_pidx = min(max((int)(s * (1.0f / NS)), 0), NBINS - 1);
    }
    __syncthreads();
    if (lane == 0) wred[warp] = e;
    __syncthreads();
    if (tid == 0) {
        float s = 0.f;
        #pragma unroll
        for (int i = 0; i < 16; i++) s += wred[i];
        s_eidx = min(max((int)(s * (1.0f / NS)), 0), NBINS - 1);
        g_mellen[b] = min(total, NL);
        if (write_tail) out_tail[b] = (float)min(total, NL);
    }
    __syncthreads();

    // ---- combined embedding row: comb = pemb[pi] + eemb[ei] ----
    if (tid < H4) {
        float4 pv = pemb[s_pidx * H4 + tid];
        float4 ev = eemb[s_eidx * H4 + tid];
        pv.x += ev.x; pv.y += ev.y; pv.z += ev.z; pv.w += ev.w;
        g_comb[b * H4 + tid] = pv;
    }

    // ---- segment scatter (no init: expand masks rows >= mellen) ----
    const int end = min(cum, NL);
    for (int l = start; l < end; ++l) g_seg[b * NL + l] = tid;
}

// grid (125, 16), block (96, 4). Each thread: column q, 4 consecutive rows.
// Minimal critical path: no smem, no barrier, no TMA. Front-batched gather
// loads, fmaf mask, streaming (evict-first) direct stores.
__global__ void __launch_bounds__(384) expand_kernel(
    const float4* __restrict__ enc,
    float4* __restrict__ out)
{
    const int q  = threadIdx.x;                 // 0..95
    const int yy = threadIdx.y;                 // 0..3
    const int b  = blockIdx.y;                  // 0..15
    const int l0 = blockIdx.x * TR;             // tile base row
    const int r0 = yy * 4;                      // my 4 consecutive rows

    const int ml = g_mellen[b];
    const int4 s4 = *(const int4*)(g_seg + b * NL + l0 + r0);
    const float4 c = g_comb[b * H4 + q];
    const float4* __restrict__ encb = enc + b * (NS * H4);

    const int sc[4] = { s4.x, s4.y, s4.z, s4.w };

    // front-batched unconditional gather loads (clamped addresses)
    float4 ev[4];
    #pragma unroll
    for (int i = 0; i < 4; i++) {
        const int s = min(max(sc[i], 0), NS - 1);
        ev[i] = __ldg(&encb[s * H4 + q]);
    }

    // masked add + streaming stores (output never re-read: evict-first)
    float4* const outp = out + (size_t)(b * NL + l0 + r0) * H4 + q;
    #pragma unroll
    for (int i = 0; i < 4; i++) {
        const float m = (l0 + r0 + i < ml) ? 1.0f : 0.0f;
        float4 v;
        v.x = fmaf(m, ev[i].x, c.x);
        v.y = fmaf(m, ev[i].y, c.y);
        v.z = fmaf(m, ev[i].z, c.z);
        v.w = fmaf(m, ev[i].w, c.w);
        __stcs(&outp[i * H4], v);
    }
}

extern "C" void kernel_launch(void* const* d_in, const int* in_sizes, int n_in,
                              void* d_out, int out_size)
{
    const float* enc   = (const float*)d_in[0];  // (B,S,H)
    const float* ldur  = (const float*)d_in[1];  // (B,S)
    const float* pitch = (const float*)d_in[2];  // (B,S)
    const float* energ = (const float*)d_in[3];  // (B,S)
    const float* pemb  = (const float*)d_in[4];  // (256,H)
    const float* eemb  = (const float*)d_in[5];  // (256,H)

    float* out = (float*)d_out;
    const int main_elems = NB * NL * NH;
    const int write_tail = (out_size >= main_elems + NB) ? 1 : 0;

    prep_kernel<<<NB, NS>>>(ldur, pitch, energ,
                            (const float4*)pemb, (const float4*)eemb,
                            out + main_elems, write_tail);

    dim3 grid(NL / TR, NB);      // 125 x 16 = 2000 CTAs
    dim3 block(96, 4);
    expand_kernel<<<grid, block>>>((const float4*)enc, (float4*)out);
}